// round 3
// baseline (speedup 1.0000x reference)
#include <cuda_runtime.h>

// PlasticNet: T=64 steps, B=32, I=128, H=256, clip=2.0
// out = [ ys (T*B*H) | h_f (B*H) | hebb_f (B*H*H) ]  float32
//
// 32 clusters of 4 CTAs (one cluster per sample). CTA c owns presynaptic rows
// [c*64, c*64+64). Thread t owns column t: 64 hebb/w/alpha scalars in regs.
// Per step, CTAs exchange 256-wide rec partials via DSMEM + mbarriers.

static constexpr int kT = 64;
static constexpr int kB = 32;
static constexpr int kI = 128;
static constexpr int kH = 256;
static constexpr int kRows = 64;                   // presynaptic rows per CTA
static constexpr int kNCTA = kB * 4;               // 128
static constexpr int kThreads = 256;

__device__ float g_xwi[kT * kB * kH];              // x@Wi + bi, precomputed

// ---------------------------------------------------------------------------
__global__ void xwi_kernel(const float* __restrict__ x,
                           const float* __restrict__ Wi,
                           const float* __restrict__ bi) {
    __shared__ float xs[kI];
    const int row = blockIdx.x;        // 0 .. T*B-1
    const int k = threadIdx.x;         // 0 .. 255
    if (k < kI) xs[k] = x[row * kI + k];
    __syncthreads();
    float acc = bi[k];
#pragma unroll 16
    for (int i = 0; i < kI; ++i)
        acc = fmaf(xs[i], Wi[i * kH + k], acc);
    g_xwi[row * kH + k] = acc;
}

// ---------------------------------------------------------------------------
// PTX helpers
// ---------------------------------------------------------------------------
__device__ __forceinline__ unsigned smem_u32(const void* p) {
    return (unsigned)__cvta_generic_to_shared(p);
}
__device__ __forceinline__ unsigned mapa_u32(unsigned addr, unsigned rank) {
    unsigned o;
    asm("mapa.shared::cluster.u32 %0, %1, %2;" : "=r"(o) : "r"(addr), "r"(rank));
    return o;
}
__device__ __forceinline__ void st_cluster_f32(unsigned addr, float v) {
    asm volatile("st.shared::cluster.f32 [%0], %1;" :: "r"(addr), "f"(v) : "memory");
}
__device__ __forceinline__ void mbar_init(unsigned addr, unsigned cnt) {
    asm volatile("mbarrier.init.shared.b64 [%0], %1;" :: "r"(addr), "r"(cnt) : "memory");
}
__device__ __forceinline__ void mbar_arrive_rel_cluster(unsigned addr) {
    asm volatile("mbarrier.arrive.release.cluster.shared::cluster.b64 _, [%0];"
                 :: "r"(addr) : "memory");
}
__device__ __forceinline__ void mbar_wait_acq_cluster(unsigned addr, unsigned phase) {
    unsigned done;
    asm volatile(
        "{\n\t.reg .pred p;\n\t"
        "mbarrier.try_wait.parity.acquire.cluster.shared::cta.b64 p, [%1], %2;\n\t"
        "selp.b32 %0, 1, 0, p;\n\t}"
        : "=r"(done) : "r"(addr), "r"(phase) : "memory");
    if (!done) {
        asm volatile(
            "{\n\t.reg .pred P1;\n\t"
            "W_%=:\n\t"
            "mbarrier.try_wait.parity.acquire.cluster.shared::cta.b64 P1, [%0], %1, 0x989680;\n\t"
            "@P1 bra.uni D_%=;\n\t"
            "bra.uni W_%=;\n\t"
            "D_%=:\n\t}"
            :: "r"(addr), "r"(phase) : "memory");
    }
}
__device__ __forceinline__ void cluster_sync_all() {
    asm volatile("barrier.cluster.arrive.aligned;" ::: "memory");
    asm volatile("barrier.cluster.wait.aligned;" ::: "memory");
}

// ---------------------------------------------------------------------------
__global__ void __launch_bounds__(kThreads, 1) __cluster_dims__(4, 1, 1)
plastic_kernel(const float* __restrict__ w,
               const float* __restrict__ alpha,
               const float* __restrict__ Wm,
               const float* __restrict__ bm,
               const float* __restrict__ Wf,
               const float* __restrict__ bf,
               float* __restrict__ out) {
    const int b = blockIdx.x >> 2;
    const int c = blockIdx.x & 3;      // cluster ctarank
    const int t = threadIdx.x;
    const int lane = t & 31;
    const int i0 = c * kRows;

    // Register-resident state: element (i0+i, t), i = 0..63
    float wv[kRows], av[kRows], hb[kRows];
#pragma unroll
    for (int i = 0; i < kRows; ++i) {
        wv[i] = __ldg(&w[(i0 + i) * kH + t]);
        av[i] = __ldg(&alpha[(i0 + i) * kH + t]);
        hb[i] = 0.f;
    }
    const float wf_t = __ldg(&Wf[t]);
    const float bf_t = __ldg(&bf[t]);
    const float bm0 = __ldg(&bm[0]);
    float wm_r[8];
#pragma unroll
    for (int q = 0; q < 8; ++q) wm_r[q] = __ldg(&Wm[q * 32 + lane]);

    __shared__ __align__(16) float hbuf[2][kH];       // h double buffer
    __shared__ __align__(16) float recv[2][4][kH];    // cluster partials, dbl buf
    __shared__ __align__(8) unsigned long long mbar[2];

    if (t == 0) { mbar_init(smem_u32(&mbar[0]), 32); mbar_init(smem_u32(&mbar[1]), 32); }
    hbuf[0][t] = 0.f;   // h_{-1} = 0
    __syncthreads();
    cluster_sync_all();   // peers' mbarriers + smem live before any remote op

    // Precompute DSMEM addresses (3 peers) for pushes and all-4 barrier arrives
    unsigned pr_addr[2][3], mb_addr[2][4];
#pragma unroll
    for (int p = 0; p < 2; ++p) {
        const unsigned lr = smem_u32(&recv[p][c][t]);
        const unsigned lm = smem_u32(&mbar[p]);
#pragma unroll
        for (int d = 1; d < 4; ++d)
            pr_addr[p][d - 1] = mapa_u32(lr, (unsigned)((c + d) & 3));
#pragma unroll
        for (int d = 0; d < 4; ++d)
            mb_addr[p][d] = mapa_u32(lm, (unsigned)((c + d) & 3));
    }

    float* __restrict__ ys = out;
    float* __restrict__ hf = out + kT * kB * kH;
    float* __restrict__ hebbf = out + kT * kB * kH + kB * kH;

    // step 0: h_{-1}=0 -> rec=0 -> h = tanh(xwi[0])
    float h_cur = tanhf(__ldg(&g_xwi[b * kH + t]));

    for (int step = 0; step < kT; ++step) {
        const int par = step & 1;
        const float* __restrict__ hp = hbuf[par];        // h_{step-1}
        float* __restrict__ hn = hbuf[par ^ 1];          // h_step

        hn[t] = h_cur;
        if (c == 0) ys[(step * kB + b) * kH + t] = h_cur;
        __syncthreads();

        // ---- eta = tanh(h . Wm + bm), redundant per warp ----
        float s = 0.f;
#pragma unroll
        for (int q = 0; q < 8; ++q)
            s = fmaf(hn[q * 32 + lane], wm_r[q], s);
#pragma unroll
        for (int off = 16; off; off >>= 1)
            s += __shfl_xor_sync(0xffffffffu, s, off);
        const float eta = tanhf(s + bm0);
        const float v = fmaf(eta, wf_t, bf_t) * h_cur;    // me_t * h_t

        // ---- fused: hebb update (uses hp) + next-step rec partial (uses hn) ----
        float pra = 0.f, prb = 0.f, prc = 0.f, prd = 0.f;
#pragma unroll
        for (int ii = 0; ii < 16; ++ii) {
            const float4 hp4 = *reinterpret_cast<const float4*>(&hp[i0 + 4 * ii]);
            const float4 hn4 = *reinterpret_cast<const float4*>(&hn[i0 + 4 * ii]);
            const int i = 4 * ii;
            hb[i + 0] = fminf(fmaxf(fmaf(v, hp4.x, hb[i + 0]), -2.f), 2.f);
            hb[i + 1] = fminf(fmaxf(fmaf(v, hp4.y, hb[i + 1]), -2.f), 2.f);
            hb[i + 2] = fminf(fmaxf(fmaf(v, hp4.z, hb[i + 2]), -2.f), 2.f);
            hb[i + 3] = fminf(fmaxf(fmaf(v, hp4.w, hb[i + 3]), -2.f), 2.f);
            pra = fmaf(hn4.x, fmaf(av[i + 0], hb[i + 0], wv[i + 0]), pra);
            prb = fmaf(hn4.y, fmaf(av[i + 1], hb[i + 1], wv[i + 1]), prb);
            prc = fmaf(hn4.z, fmaf(av[i + 2], hb[i + 2], wv[i + 2]), prc);
            prd = fmaf(hn4.w, fmaf(av[i + 3], hb[i + 3], wv[i + 3]), prd);
        }

        if (step < kT - 1) {
            const float pr = (pra + prb) + (prc + prd);
            const int np = par ^ 1;
            // push partial to self + 3 peers
            recv[np][c][t] = pr;
            st_cluster_f32(pr_addr[np][0], pr);
            st_cluster_f32(pr_addr[np][1], pr);
            st_cluster_f32(pr_addr[np][2], pr);
            __syncwarp();
            if (lane == 0) {
                mbar_arrive_rel_cluster(mb_addr[np][0]);
                mbar_arrive_rel_cluster(mb_addr[np][1]);
                mbar_arrive_rel_cluster(mb_addr[np][2]);
                mbar_arrive_rel_cluster(mb_addr[np][3]);
            }
            // prefetch next xwi under barrier latency
            const float xw = __ldg(&g_xwi[((step + 1) * kB + b) * kH + t]);
            // wait for all 32 warp-arrivals (4 CTAs x 8 warps)
            mbar_wait_acq_cluster(smem_u32(&mbar[np]), (unsigned)((step >> 1) & 1));
            const float hsum = (recv[np][0][t] + recv[np][1][t]) +
                               (recv[np][2][t] + recv[np][3][t]);
            h_cur = tanhf(xw + hsum);
        }
    }

    // ---- final outputs ----
    if (c == 0) hf[b * kH + t] = h_cur;    // h at step T-1
#pragma unroll
    for (int i = 0; i < kRows; ++i)
        hebbf[(size_t)b * kH * kH + (i0 + i) * kH + t] = hb[i];
}

// ---------------------------------------------------------------------------
extern "C" void kernel_launch(void* const* d_in, const int* in_sizes, int n_in,
                              void* d_out, int out_size) {
    const float* x     = (const float*)d_in[0];
    const float* Wi    = (const float*)d_in[1];
    const float* bi    = (const float*)d_in[2];
    const float* w     = (const float*)d_in[3];
    const float* alpha = (const float*)d_in[4];
    const float* Wm    = (const float*)d_in[5];
    const float* bm    = (const float*)d_in[6];
    const float* Wf    = (const float*)d_in[7];
    const float* bf    = (const float*)d_in[8];
    float* out = (float*)d_out;

    xwi_kernel<<<kT * kB, kThreads>>>(x, Wi, bi);
    plastic_kernel<<<kNCTA, kThreads>>>(w, alpha, Wm, bm, Wf, bf, out);
}

// round 4
// speedup vs baseline: 1.4802x; 1.4802x over previous
#include <cuda_runtime.h>

// PlasticNet: T=64 steps, B=32, I=128, H=256, clip=2.0
// out = [ ys (T*B*H) | h_f (B*H) | hebb_f (B*H*H) ]  float32
//
// 32 clusters of 4 CTAs (one cluster per sample). CTA c owns presynaptic rows
// [c*64, c*64+64). Thread t owns column t: 64 hebb/w/alpha scalars in regs.
// Per step: CTAs push 256-wide rec partials into peers' SMEM (DSMEM), then one
// cluster barrier (arrive/wait split) orders delivery.

static constexpr int kT = 64;
static constexpr int kB = 32;
static constexpr int kI = 128;
static constexpr int kH = 256;
static constexpr int kRows = 64;                   // presynaptic rows per CTA
static constexpr int kNCTA = kB * 4;               // 128
static constexpr int kThreads = 256;

__device__ float g_xwi[kT * kB * kH];              // x@Wi + bi, precomputed

// ---------------------------------------------------------------------------
__global__ void xwi_kernel(const float* __restrict__ x,
                           const float* __restrict__ Wi,
                           const float* __restrict__ bi) {
    __shared__ float xs[kI];
    const int row = blockIdx.x;        // 0 .. T*B-1
    const int k = threadIdx.x;         // 0 .. 255
    if (k < kI) xs[k] = x[row * kI + k];
    __syncthreads();
    float acc = bi[k];
#pragma unroll 16
    for (int i = 0; i < kI; ++i)
        acc = fmaf(xs[i], Wi[i * kH + k], acc);
    g_xwi[row * kH + k] = acc;
}

// ---------------------------------------------------------------------------
// PTX helpers
// ---------------------------------------------------------------------------
__device__ __forceinline__ unsigned smem_u32(const void* p) {
    return (unsigned)__cvta_generic_to_shared(p);
}
__device__ __forceinline__ unsigned mapa_u32(unsigned addr, unsigned rank) {
    unsigned o;
    asm("mapa.shared::cluster.u32 %0, %1, %2;" : "=r"(o) : "r"(addr), "r"(rank));
    return o;
}
__device__ __forceinline__ void st_cluster_f32(unsigned addr, float v) {
    asm volatile("st.shared::cluster.f32 [%0], %1;" :: "r"(addr), "f"(v) : "memory");
}
__device__ __forceinline__ void cluster_arrive() {
    asm volatile("barrier.cluster.arrive.aligned;" ::: "memory");
}
__device__ __forceinline__ void cluster_wait() {
    asm volatile("barrier.cluster.wait.aligned;" ::: "memory");
}

// ---------------------------------------------------------------------------
__global__ void __launch_bounds__(kThreads, 1) __cluster_dims__(4, 1, 1)
plastic_kernel(const float* __restrict__ w,
               const float* __restrict__ alpha,
               const float* __restrict__ Wm,
               const float* __restrict__ bm,
               const float* __restrict__ Wf,
               const float* __restrict__ bf,
               float* __restrict__ out) {
    const int b = blockIdx.x >> 2;
    const int c = blockIdx.x & 3;      // cluster ctarank
    const int t = threadIdx.x;
    const int lane = t & 31;
    const int wid = t >> 5;
    const int i0 = c * kRows;

    // Register-resident state: element (i0+i, t), i = 0..63
    float wv[kRows], av[kRows], hb[kRows];
#pragma unroll
    for (int i = 0; i < kRows; ++i) {
        wv[i] = __ldg(&w[(i0 + i) * kH + t]);
        av[i] = __ldg(&alpha[(i0 + i) * kH + t]);
        hb[i] = 0.f;
    }
    const float wf_t = __ldg(&Wf[t]);
    const float bf_t = __ldg(&bf[t]);
    const float wm_t = __ldg(&Wm[t]);
    const float bm0 = __ldg(&bm[0]);

    __shared__ __align__(16) float hbuf[2][kH];       // h double buffer
    __shared__ __align__(16) float recv[2][4][kH];    // cluster partials, dbl buf
    __shared__ __align__(16) float wpart[8];          // per-warp eta partials

    hbuf[0][t] = 0.f;   // h_{-1} = 0
    __syncthreads();
    cluster_arrive();   // peers' smem live before any remote store
    cluster_wait();

    // DSMEM push addresses for the 3 peers (both parities)
    unsigned pr_addr[2][3];
#pragma unroll
    for (int p = 0; p < 2; ++p) {
        const unsigned lr = smem_u32(&recv[p][c][t]);
#pragma unroll
        for (int d = 1; d < 4; ++d)
            pr_addr[p][d - 1] = mapa_u32(lr, (unsigned)((c + d) & 3));
    }

    float* __restrict__ ys = out;
    float* __restrict__ hf = out + kT * kB * kH;
    float* __restrict__ hebbf = out + kT * kB * kH + kB * kH;

    // step 0: h_{-1}=0 -> rec=0 -> h = tanh(xwi[0])
    float h_cur = tanhf(__ldg(&g_xwi[b * kH + t]));

    for (int step = 0; step < kT; ++step) {
        const int par = step & 1;
        const float* __restrict__ hp = hbuf[par];        // h_{step-1}
        float* __restrict__ hn = hbuf[par ^ 1];          // h_step

        hn[t] = h_cur;
        // eta partial: this warp's 32 columns, reduced pre-sync
        float s = h_cur * wm_t;
#pragma unroll
        for (int off = 16; off; off >>= 1)
            s += __shfl_xor_sync(0xffffffffu, s, off);
        if (lane == 0) wpart[wid] = s;
        if (c == 0) ys[(step * kB + b) * kH + t] = h_cur;
        __syncthreads();

        // ---- eta = tanh(h . Wm + bm) ----
        const float4 wp0 = *reinterpret_cast<const float4*>(&wpart[0]);
        const float4 wp1 = *reinterpret_cast<const float4*>(&wpart[4]);
        const float eta = tanhf(((wp0.x + wp0.y) + (wp0.z + wp0.w)) +
                                ((wp1.x + wp1.y) + (wp1.z + wp1.w)) + bm0);
        const float v = fmaf(eta, wf_t, bf_t) * h_cur;    // me_t * h_t

        // ---- fused: hebb update (uses hp) + next-step rec partial (uses hn) ----
        float pra = 0.f, prb = 0.f, prc = 0.f, prd = 0.f;
#pragma unroll
        for (int ii = 0; ii < 16; ++ii) {
            const float4 hp4 = *reinterpret_cast<const float4*>(&hp[i0 + 4 * ii]);
            const float4 hn4 = *reinterpret_cast<const float4*>(&hn[i0 + 4 * ii]);
            const int i = 4 * ii;
            hb[i + 0] = fminf(fmaxf(fmaf(v, hp4.x, hb[i + 0]), -2.f), 2.f);
            hb[i + 1] = fminf(fmaxf(fmaf(v, hp4.y, hb[i + 1]), -2.f), 2.f);
            hb[i + 2] = fminf(fmaxf(fmaf(v, hp4.z, hb[i + 2]), -2.f), 2.f);
            hb[i + 3] = fminf(fmaxf(fmaf(v, hp4.w, hb[i + 3]), -2.f), 2.f);
            pra = fmaf(hn4.x, fmaf(av[i + 0], hb[i + 0], wv[i + 0]), pra);
            prb = fmaf(hn4.y, fmaf(av[i + 1], hb[i + 1], wv[i + 1]), prb);
            prc = fmaf(hn4.z, fmaf(av[i + 2], hb[i + 2], wv[i + 2]), prc);
            prd = fmaf(hn4.w, fmaf(av[i + 3], hb[i + 3], wv[i + 3]), prd);
        }

        if (step < kT - 1) {
            const float pr = (pra + prb) + (prc + prd);
            const int np = par ^ 1;
            // push partial to self + 3 peers
            recv[np][c][t] = pr;
            st_cluster_f32(pr_addr[np][0], pr);
            st_cluster_f32(pr_addr[np][1], pr);
            st_cluster_f32(pr_addr[np][2], pr);
            // barrier arrive has release semantics: orders the pushes
            cluster_arrive();
            // shadow work under the barrier
            const float xw = __ldg(&g_xwi[((step + 1) * kB + b) * kH + t]);
            cluster_wait();
            const float hsum = (recv[np][0][t] + recv[np][1][t]) +
                               (recv[np][2][t] + recv[np][3][t]);
            h_cur = tanhf(xw + hsum);
        }
    }

    // ---- final outputs ----
    if (c == 0) hf[b * kH + t] = h_cur;    // h at step T-1
#pragma unroll
    for (int i = 0; i < kRows; ++i)
        hebbf[(size_t)b * kH * kH + (i0 + i) * kH + t] = hb[i];
}

// ---------------------------------------------------------------------------
extern "C" void kernel_launch(void* const* d_in, const int* in_sizes, int n_in,
                              void* d_out, int out_size) {
    const float* x     = (const float*)d_in[0];
    const float* Wi    = (const float*)d_in[1];
    const float* bi    = (const float*)d_in[2];
    const float* w     = (const float*)d_in[3];
    const float* alpha = (const float*)d_in[4];
    const float* Wm    = (const float*)d_in[5];
    const float* bm    = (const float*)d_in[6];
    const float* Wf    = (const float*)d_in[7];
    const float* bf    = (const float*)d_in[8];
    float* out = (float*)d_out;

    xwi_kernel<<<kT * kB, kThreads>>>(x, Wi, bi);
    plastic_kernel<<<kNCTA, kThreads>>>(w, alpha, Wm, bm, Wf, bf, out);
}